// round 8
// baseline (speedup 1.0000x reference)
#include <cuda_runtime.h>
#include <cstdint>

// N = 16777216, pred: float32 (N,2), target: int64 in reference (device layout
// detected in-kernel: int32 or int64; measured traffic confirms int32).
// Output: scalar float mean loss.
// Single persistent-wave HBM-streaming reduction: ~201 MB read, 4 B written.
// R5 structure, but 4 blocks/SM (64 regs/thread) so ptxas can front-batch
// ~16 loads/warp: SM-wide MLP nearly doubles vs the 32-reg configuration.

static constexpr int N_ELEMS = 16777216;
static constexpr float INV_N = 1.0f / 16777216.0f;

static constexpr int BLOCKS  = 148 * 4;                   // 592 = one full wave @4/SM
static constexpr int THREADS = 256;
static constexpr int TOTAL   = BLOCKS * THREADS;          // 151552
static constexpr int NPAIRS  = N_ELEMS / 2;               // 8388608 (55.4 iters/thread)

// Cross-block reduction state. Zero at module load; last block resets each
// run so every graph replay starts clean.
__device__ float g_partial;
__device__ unsigned int g_count;

__device__ __forceinline__ float elem_loss(float p0, float p1, bool z) {
    float a = z ? p0 : p1;   // correct-class prob
    float b = z ? p1 : p0;   // other prob
    float d = 1.0f - a;
    float sq = fmaf(d, d, b * b);
    return sq + (a < b ? 2.0f : 0.0f);
}

__global__ void __launch_bounds__(THREADS, 4) custom_loss_kernel(
    const float4* __restrict__ pred4,   // pred4[i] = rows 2i and 2i+1
    const void* __restrict__ tgt,
    float* __restrict__ out)
{
    // ---- in-kernel layout detection (uniform per block) ----
    // Odd 32-bit words among the first 128 words: all zero iff targets are
    // int64 0/1 (their high words); ~half nonzero if int32. In-bounds always.
    __shared__ int s_i32;
    if (threadIdx.x == 0) s_i32 = 0;
    __syncthreads();
    if (threadIdx.x < 64) {
        if (((const int*)tgt)[2 * threadIdx.x + 1] != 0) s_i32 = 1;
    }
    __syncthreads();
    const bool i32 = (s_i32 != 0);

    const int gid = blockIdx.x * THREADS + threadIdx.x;

    float acc0 = 0.0f, acc1 = 0.0f;

    if (i32) {
        const int2* __restrict__ t2 = (const int2*)tgt;   // 2 targets per int2
        #pragma unroll 16
        for (int i = gid; i < NPAIRS; i += TOTAL) {
            float4 p = __ldg(pred4 + i);
            int2 t = __ldg(t2 + i);
            acc0 += elem_loss(p.x, p.y, t.x == 0);
            acc1 += elem_loss(p.z, p.w, t.y == 0);
        }
    } else {
        const ulonglong2* __restrict__ t2 = (const ulonglong2*)tgt;
        #pragma unroll 16
        for (int i = gid; i < NPAIRS; i += TOTAL) {
            float4 p = __ldg(pred4 + i);
            ulonglong2 t = __ldg(t2 + i);
            acc0 += elem_loss(p.x, p.y, t.x == 0ULL);
            acc1 += elem_loss(p.z, p.w, t.y == 0ULL);
        }
    }

    float acc = acc0 + acc1;

    // ---- intra-block reduce ----
    #pragma unroll
    for (int o = 16; o > 0; o >>= 1)
        acc += __shfl_xor_sync(0xFFFFFFFFu, acc, o);

    __shared__ float smem[THREADS / 32];
    int lane = threadIdx.x & 31;
    int warp = threadIdx.x >> 5;
    if (lane == 0) smem[warp] = acc;
    __syncthreads();

    if (threadIdx.x == 0) {
        float bsum = 0.0f;
        #pragma unroll
        for (int w = 0; w < THREADS / 32; w++) bsum += smem[w];

        // ---- cross-block: accumulate, last block finalizes + resets ----
        atomicAdd(&g_partial, bsum * INV_N);
        __threadfence();
        unsigned prev = atomicAdd(&g_count, 1u);
        if (prev == gridDim.x - 1) {
            float total = atomicExch(&g_partial, 0.0f);  // read + reset
            out[0] = total;
            atomicExch(&g_count, 0u);
        }
    }
}

extern "C" void kernel_launch(void* const* d_in, const int* in_sizes, int n_in,
                              void* d_out, int out_size) {
    const float4* pred4 = (const float4*)d_in[0];
    const void* tgt = d_in[1];
    float* out = (float*)d_out;

    custom_loss_kernel<<<BLOCKS, THREADS>>>(pred4, tgt, out);
}

// round 9
// speedup vs baseline: 1.0378x; 1.0378x over previous
#include <cuda_runtime.h>
#include <cstdint>

// N = 16777216, pred: float32 (N,2), target: int64 in reference (device layout
// detected in-kernel: int32 or int64; measured traffic confirms int32).
// Output: scalar float mean loss.
// Single-wave HBM-streaming reduction: ~192 MB read, 4 B written.
// sm_103a 256-bit loads (ld.global.nc.v8.f32): one 32B pred load + one 16B
// target load per 4 rows -> half the LDG issue count, max-width requests.

static constexpr int N_ELEMS = 16777216;
static constexpr float INV_N = 1.0f / 16777216.0f;

static constexpr int BLOCKS  = 148 * 4;                   // 592 = one wave @4/SM
static constexpr int THREADS = 256;
static constexpr int TOTAL   = BLOCKS * THREADS;          // 151552
static constexpr int NQUADS  = N_ELEMS / 4;               // 4194304 (~27.7 iters/thread)

// Cross-block reduction state. Zero at module load; last block resets each
// run so every graph replay starts clean.
__device__ float g_partial;
__device__ unsigned int g_count;

__device__ __forceinline__ float elem_loss(float p0, float p1, bool z) {
    float a = z ? p0 : p1;   // correct-class prob
    float b = z ? p1 : p0;   // other prob
    float d = 1.0f - a;
    float sq = fmaf(d, d, b * b);
    return sq + (a < b ? 2.0f : 0.0f);
}

// 256-bit non-coherent global load (sm_100+). addr must be 32B-aligned.
__device__ __forceinline__ void ldg256(const float* p,
                                       float& a0, float& a1, float& a2, float& a3,
                                       float& a4, float& a5, float& a6, float& a7) {
    asm volatile("ld.global.nc.v8.f32 {%0,%1,%2,%3,%4,%5,%6,%7}, [%8];"
                 : "=f"(a0), "=f"(a1), "=f"(a2), "=f"(a3),
                   "=f"(a4), "=f"(a5), "=f"(a6), "=f"(a7)
                 : "l"(p));
}

__global__ void __launch_bounds__(THREADS, 4) custom_loss_kernel(
    const float* __restrict__ pred,     // row-major (N,2): float 2k = p0[k], 2k+1 = p1[k]
    const void* __restrict__ tgt,
    float* __restrict__ out)
{
    // ---- in-kernel layout detection (uniform per block) ----
    // Odd 32-bit words among the first 128 words: all zero iff targets are
    // int64 0/1 (their high words); ~half nonzero if int32. In-bounds always.
    __shared__ int s_i32;
    if (threadIdx.x == 0) s_i32 = 0;
    __syncthreads();
    if (threadIdx.x < 64) {
        if (((const int*)tgt)[2 * threadIdx.x + 1] != 0) s_i32 = 1;
    }
    __syncthreads();
    const bool i32 = (s_i32 != 0);

    const int gid = blockIdx.x * THREADS + threadIdx.x;

    float acc0 = 0.0f, acc1 = 0.0f;

    if (i32) {
        const int4* __restrict__ t4 = (const int4*)tgt;   // 4 targets per int4
        #pragma unroll 4
        for (int i = gid; i < NQUADS; i += TOTAL) {
            float a0, a1, a2, a3, a4, a5, a6, a7;
            ldg256(pred + 8ll * i, a0, a1, a2, a3, a4, a5, a6, a7);
            int4 t = __ldg(t4 + i);
            acc0 += elem_loss(a0, a1, t.x == 0);
            acc1 += elem_loss(a2, a3, t.y == 0);
            acc0 += elem_loss(a4, a5, t.z == 0);
            acc1 += elem_loss(a6, a7, t.w == 0);
        }
    } else {
        const ulonglong2* __restrict__ t2 = (const ulonglong2*)tgt;
        #pragma unroll 4
        for (int i = gid; i < NQUADS; i += TOTAL) {
            float a0, a1, a2, a3, a4, a5, a6, a7;
            ldg256(pred + 8ll * i, a0, a1, a2, a3, a4, a5, a6, a7);
            ulonglong2 ta = __ldg(t2 + 2 * i);
            ulonglong2 tb = __ldg(t2 + 2 * i + 1);
            acc0 += elem_loss(a0, a1, ta.x == 0ULL);
            acc1 += elem_loss(a2, a3, ta.y == 0ULL);
            acc0 += elem_loss(a4, a5, tb.x == 0ULL);
            acc1 += elem_loss(a6, a7, tb.y == 0ULL);
        }
    }

    float acc = acc0 + acc1;

    // ---- intra-block reduce ----
    #pragma unroll
    for (int o = 16; o > 0; o >>= 1)
        acc += __shfl_xor_sync(0xFFFFFFFFu, acc, o);

    __shared__ float smem[THREADS / 32];
    int lane = threadIdx.x & 31;
    int warp = threadIdx.x >> 5;
    if (lane == 0) smem[warp] = acc;
    __syncthreads();

    if (threadIdx.x == 0) {
        float bsum = 0.0f;
        #pragma unroll
        for (int w = 0; w < THREADS / 32; w++) bsum += smem[w];

        // ---- cross-block: accumulate, last block finalizes + resets ----
        atomicAdd(&g_partial, bsum * INV_N);
        __threadfence();
        unsigned prev = atomicAdd(&g_count, 1u);
        if (prev == gridDim.x - 1) {
            float total = atomicExch(&g_partial, 0.0f);  // read + reset
            out[0] = total;
            atomicExch(&g_count, 0u);
        }
    }
}

extern "C" void kernel_launch(void* const* d_in, const int* in_sizes, int n_in,
                              void* d_out, int out_size) {
    const float* pred = (const float*)d_in[0];
    const void* tgt = d_in[1];
    float* out = (float*)d_out;

    custom_loss_kernel<<<BLOCKS, THREADS>>>(pred, tgt, out);
}

// round 11
// speedup vs baseline: 1.0453x; 1.0072x over previous
#include <cuda_runtime.h>
#include <cstdint>

// N = 16777216, pred: float32 (N,2), target: int64 in reference (device layout
// detected in-kernel: int32 or int64), output: scalar float mean loss.
// Single persistent-wave HBM-streaming reduction: ~192 MB read, 4 B written.
// 1184 blocks = 148 SMs x 8 resident blocks -> exactly one wave, no tail.
// FINAL: best validated configuration (R5). Sweeps over occupancy (45-96%),
// unroll (4-16), load width (128/256b), cache policy, and grid shape all
// measured the same ~5.8 TB/s structural plateau; this config won.

static constexpr int N_ELEMS = 16777216;
static constexpr float INV_N = 1.0f / 16777216.0f;

static constexpr int BLOCKS  = 148 * 8;                   // 1184 = one full wave
static constexpr int THREADS = 256;
static constexpr int TOTAL   = BLOCKS * THREADS;          // 303104
static constexpr int NPAIRS  = N_ELEMS / 2;               // 8388608 (27.68 iters/thread)

// Cross-block reduction state. Zero at module load; last block resets each
// run so every graph replay starts clean.
__device__ float g_partial;
__device__ unsigned int g_count;

__device__ __forceinline__ float elem_loss(float p0, float p1, bool z) {
    float a = z ? p0 : p1;   // correct-class prob
    float b = z ? p1 : p0;   // other prob
    float d = 1.0f - a;
    float sq = fmaf(d, d, b * b);
    return sq + (a < b ? 2.0f : 0.0f);
}

__global__ void __launch_bounds__(THREADS) custom_loss_kernel(
    const float4* __restrict__ pred4,   // pred4[i] = rows 2i and 2i+1
    const void* __restrict__ tgt,
    float* __restrict__ out)
{
    // ---- in-kernel layout detection (uniform per block) ----
    // Odd 32-bit words among the first 128 words: all zero iff targets are
    // int64 0/1 (their high words); ~half nonzero if int32. In-bounds always.
    __shared__ int s_i32;
    if (threadIdx.x == 0) s_i32 = 0;
    __syncthreads();
    if (threadIdx.x < 64) {
        if (((const int*)tgt)[2 * threadIdx.x + 1] != 0) s_i32 = 1;
    }
    __syncthreads();
    const bool i32 = (s_i32 != 0);

    const int gid = blockIdx.x * THREADS + threadIdx.x;

    float acc = 0.0f;

    if (i32) {
        const int2* __restrict__ t2 = (const int2*)tgt;   // 2 targets per int2
        #pragma unroll 4
        for (int i = gid; i < NPAIRS; i += TOTAL) {
            float4 p = __ldg(pred4 + i);
            int2 t = __ldg(t2 + i);
            acc += elem_loss(p.x, p.y, t.x == 0);
            acc += elem_loss(p.z, p.w, t.y == 0);
        }
    } else {
        const ulonglong2* __restrict__ t2 = (const ulonglong2*)tgt;
        #pragma unroll 4
        for (int i = gid; i < NPAIRS; i += TOTAL) {
            float4 p = __ldg(pred4 + i);
            ulonglong2 t = __ldg(t2 + i);
            acc += elem_loss(p.x, p.y, t.x == 0ULL);
            acc += elem_loss(p.z, p.w, t.y == 0ULL);
        }
    }

    // ---- intra-block reduce ----
    #pragma unroll
    for (int o = 16; o > 0; o >>= 1)
        acc += __shfl_xor_sync(0xFFFFFFFFu, acc, o);

    __shared__ float smem[THREADS / 32];
    int lane = threadIdx.x & 31;
    int warp = threadIdx.x >> 5;
    if (lane == 0) smem[warp] = acc;
    __syncthreads();

    if (threadIdx.x == 0) {
        float bsum = 0.0f;
        #pragma unroll
        for (int w = 0; w < THREADS / 32; w++) bsum += smem[w];

        // ---- cross-block: accumulate, last block finalizes + resets ----
        atomicAdd(&g_partial, bsum * INV_N);
        __threadfence();
        unsigned prev = atomicAdd(&g_count, 1u);
        if (prev == gridDim.x - 1) {
            float total = atomicExch(&g_partial, 0.0f);  // read + reset
            out[0] = total;
            atomicExch(&g_count, 0u);
        }
    }
}

extern "C" void kernel_launch(void* const* d_in, const int* in_sizes, int n_in,
                              void* d_out, int out_size) {
    const float4* pred4 = (const float4*)d_in[0];
    const void* tgt = d_in[1];
    float* out = (float*)d_out;

    custom_loss_kernel<<<BLOCKS, THREADS>>>(pred4, tgt, out);
}